// round 8
// baseline (speedup 1.0000x reference)
#include <cuda_runtime.h>
#include <cuda_fp16.h>
#include <mma.h>
#include <stdint.h>

using namespace nvcuda;

// Problem dims
#define BATCH   256
#define TSEQ    1024
#define IN_D    128
#define HID     256
#define OUT_D   128

// Partitioning: 16 batch-groups x 8 unit-group CTAs (cluster of 8 per batch group)
#define NBG     16
#define NUG     8
#define MB      16            // batch rows per group
#define UPC     32            // hidden units per CTA
#define NROWS   128           // gate rows per CTA
#define KDIM    384           // [h(256) | x(128)]
#define KPAD    392           // padded K stride (halves)
#define ZPAD    132           // padded z stride (floats)
#define NTH     256
#define KH      16            // h-part k-steps
#define KSTEPS  24

#define SW_ELEMS (NROWS*KPAD)          // 50176 halves
#define SA_ELEMS (MB*KPAD)             // 6272 halves per buffer

// smem byte offsets
#define OFF_MBAR 0                                  // 2 x u64 mbarriers
#define OFF_SW   16
#define OFF_SA   (OFF_SW + SW_ELEMS*2)              // 100368
#define OFF_SZ   (OFF_SA + 2*SA_ELEMS*2)            // 125456
#define OFF_SB   (OFF_SZ + MB*ZPAD*4)               // 133904
#define OFF_SH   (OFF_SB + NROWS*4)                 // 134416
#define SMEM_BYTES (OFF_SH + MB*UPC*2)              // 135440

__device__ float g_h32[BATCH*HID];   // fp32 h_T for final projection

__device__ __forceinline__ float tanh_fast(float x) {
    float e = __expf(2.0f * x);
    return 1.0f - 2.0f / (e + 1.0f);
}
__device__ __forceinline__ float sigm_fast(float x) {
    return 1.0f / (1.0f + __expf(-x));
}
__device__ __forceinline__ uint32_t elect1() {
    uint32_t p;
    asm volatile("{\n\t.reg .pred p;\n\telect.sync _|p, 0xFFFFFFFF;\n\tselp.b32 %0,1,0,p;\n\t}"
                 : "=r"(p));
    return p;
}
__device__ __forceinline__ void mbar_wait_cluster(uint32_t mbar, uint32_t parity) {
    asm volatile(
        "{\n\t.reg .pred P;\n"
        "WL_%=:\n\t"
        "mbarrier.try_wait.parity.acquire.cluster.shared::cta.b64 P, [%0], %1, 0x989680;\n\t"
        "@P bra.uni WD_%=;\n\t"
        "bra.uni WL_%=;\n"
        "WD_%=:\n\t}"
        :: "r"(mbar), "r"(parity) : "memory");
}
__device__ __forceinline__ void remote_st_v4(uint32_t dst_local, uint32_t rank, uint4 v) {
    asm volatile(
        "{\n\t.reg .b32 ra;\n\t"
        "mapa.shared::cluster.u32 ra, %0, %1;\n\t"
        "st.shared::cluster.v4.u32 [ra], {%2,%3,%4,%5};\n\t}"
        :: "r"(dst_local), "r"(rank), "r"(v.x), "r"(v.y), "r"(v.z), "r"(v.w)
        : "memory");
}
__device__ __forceinline__ void remote_arrive(uint32_t mbar_local, uint32_t rank) {
    asm volatile(
        "{\n\t.reg .b32 ra;\n\t"
        "mapa.shared::cluster.u32 ra, %0, %1;\n\t"
        "mbarrier.arrive.release.cluster.shared::cluster.b64 _, [ra];\n\t}"
        :: "r"(mbar_local), "r"(rank)
        : "memory");
}

__global__ void __launch_bounds__(NTH, 1) __cluster_dims__(NUG, 1, 1)
lstm_mb_kernel(const float* __restrict__ x,
               const float* __restrict__ Wgx, const float* __restrict__ bgx, const float* __restrict__ Wgh,
               const float* __restrict__ Wix, const float* __restrict__ bix, const float* __restrict__ Wih,
               const float* __restrict__ Wfx, const float* __restrict__ bfx, const float* __restrict__ Wfh,
               const float* __restrict__ Wox, const float* __restrict__ boxp, const float* __restrict__ Woh,
               const float* __restrict__ Wp, const float* __restrict__ bp,
               float* __restrict__ out)
{
    extern __shared__ unsigned char smem_raw[];
    const uint32_t smb = (uint32_t)__cvta_generic_to_shared(smem_raw);
    __half* sW    = (__half*)(smem_raw + OFF_SW);
    __half* sA    = (__half*)(smem_raw + OFF_SA);     // [2][MB][KPAD]
    float*  sZ    = (float*)(smem_raw + OFF_SZ);
    float*  sBias = (float*)(smem_raw + OFF_SB);
    __half* sH    = (__half*)(smem_raw + OFF_SH);     // [MB][UPC]

    const int tid  = threadIdx.x;
    const int warp = tid >> 5;
    const int lid  = tid & 31;
    const int ug   = blockIdx.x % NUG;     // cluster rank
    const int bg   = blockIdx.x / NUG;

    // ---- mbarrier init (full[0], full[1], count = NUG arrivals each) ----
    if (tid == 0) {
        asm volatile("mbarrier.init.shared.b64 [%0], %1;" :: "r"(smb + OFF_MBAR),     "r"((uint32_t)NUG) : "memory");
        asm volatile("mbarrier.init.shared.b64 [%0], %1;" :: "r"(smb + OFF_MBAR + 8), "r"((uint32_t)NUG) : "memory");
    }

    // ---- Load weight slice into smem fp16: row n = gate*32+u, cols [Wh(256)|Wx(128)] ----
    {
        const float* WhA[4] = {Wgh, Wih, Wfh, Woh};
        const float* WxA[4] = {Wgx, Wix, Wfx, Wox};
        #pragma unroll
        for (int g = 0; g < 4; ++g) {
            const float* wh = WhA[g];
            const float* wx = WxA[g];
            for (int idx = tid; idx < UPC*KDIM; idx += NTH) {
                int ul = idx / KDIM;
                int k  = idx - ul*KDIM;
                int n  = g*UPC + ul;
                int ugl = ug*UPC + ul;
                float w = (k < HID) ? wh[ugl*HID + k] : wx[ugl*IN_D + (k - HID)];
                sW[n*KPAD + k] = __float2half_rn(w);
            }
        }
        if (tid < UPC) {
            const float* bxA[4] = {bgx, bix, bfx, boxp};
            #pragma unroll
            for (int g = 0; g < 4; ++g)
                sBias[g*UPC + tid] = bxA[g][ug*UPC + tid];
        }
    }

    // ---- Init: zero h region of buf0; x_0 -> buf0.x, x_1 -> buf1.x ----
    {
        for (int i = tid; i < MB*HID/2; i += NTH) {
            int row = i >> 7;
            int w2  = i & 127;
            *(uint32_t*)&sA[row*KPAD + w2*2] = 0u;
        }
        int row = tid >> 4;
        int q   = (tid & 15) * 8;
        #pragma unroll
        for (int bu = 0; bu < 2; ++bu) {     // bu=0 -> x_0 in buf0, bu=1 -> x_1 in buf1
            const float* src = &x[(bg*MB + row)*(TSEQ*IN_D) + bu*IN_D + q];
            float4 v0 = *(const float4*)src;
            float4 v1 = *(const float4*)(src + 4);
            __half2 h0 = __floats2half2_rn(v0.x, v0.y), h1 = __floats2half2_rn(v0.z, v0.w);
            __half2 h2 = __floats2half2_rn(v1.x, v1.y), h3 = __floats2half2_rn(v1.z, v1.w);
            uint4 pk; pk.x = *(uint32_t*)&h0; pk.y = *(uint32_t*)&h1;
            pk.z = *(uint32_t*)&h2; pk.w = *(uint32_t*)&h3;
            *(uint4*)&sA[bu*SA_ELEMS + row*KPAD + HID + q] = pk;
        }
    }
    __syncthreads();

    // cluster-wide: all mbarriers/smem init done before any DSMEM traffic
    asm volatile("barrier.cluster.arrive.aligned;" ::: "memory");
    asm volatile("barrier.cluster.wait.aligned;"   ::: "memory");

    // ---- B fragments in registers (loop-invariant weights) ----
    wmma::fragment<wmma::matrix_a, 16,16,16, __half, wmma::row_major> fa;
    wmma::fragment<wmma::matrix_b, 16,16,16, __half, wmma::col_major> fbr[KSTEPS];
    wmma::fragment<wmma::accumulator, 16,16,16, float> fc;
    const int n0 = warp * 16;
    #pragma unroll
    for (int kk = 0; kk < KSTEPS; ++kk)
        wmma::load_matrix_sync(fbr[kk], sW + n0*KPAD + kk*16, KPAD);

    // ---- Pre-loop X phase: fc = x_0 @ Wx^T (from buf0.x) ----
    wmma::fill_fragment(fc, 0.0f);
    #pragma unroll
    for (int kk = KH; kk < KSTEPS; ++kk) {
        wmma::load_matrix_sync(fa, sA + kk*16, KPAD);
        wmma::mma_sync(fc, fa, fbr[kk], fc);
    }

    // epilogue mapping
    const int b0 = tid >> 5;
    const int uu = tid & 31;
    float c0 = 0.0f, c1 = 0.0f;
    uint32_t ph[2] = {0u, 0u};

    for (int t = 0; t < TSEQ; ++t) {
        const int p = t & 1;

        // ---- prefetch x_{t+2} into regs (off critical path) ----
        float4 xv0, xv1;
        {
            int tn  = (t + 2 < TSEQ) ? (t + 2) : (TSEQ - 1);
            int row = tid >> 4;
            int q   = (tid & 15) * 8;
            const float* src = &x[(bg*MB + row)*(TSEQ*IN_D) + tn*IN_D + q];
            xv0 = *(const float4*)src;
            xv1 = *(const float4*)(src + 4);
        }

        // ---- wait for h tile (buffer p) ----
        if (t > 0) {
            mbar_wait_cluster(smb + OFF_MBAR + p*8, ph[p]);
            ph[p] ^= 1;
        }

        // ---- Phase H: accumulate h-part (k = 0..255) onto fc (already has x-part) ----
        const __half* sAp = sA + p*SA_ELEMS;
        #pragma unroll
        for (int kk = 0; kk < KH; ++kk) {
            wmma::load_matrix_sync(fa, sAp + kk*16, KPAD);
            wmma::mma_sync(fc, fa, fbr[kk], fc);
        }
        wmma::store_matrix_sync(sZ + n0, fc, ZPAD, wmma::mem_row_major);
        __syncthreads();

        // ---- Epilogue: gates, c/h update -> sH ----
        #pragma unroll
        for (int j = 0; j < 2; ++j) {
            int b = b0 + j*8;
            const float* zr = &sZ[b*ZPAD];
            float zg = zr[uu]          + sBias[uu];
            float zi = zr[UPC   + uu]  + sBias[UPC   + uu];
            float zf = zr[2*UPC + uu]  + sBias[2*UPC + uu];
            float zo = zr[3*UPC + uu]  + sBias[3*UPC + uu];
            float gv = tanh_fast(zg);
            float iv = sigm_fast(zi);
            float fv = sigm_fast(zf);
            float ov = sigm_fast(zo);
            float& c = j ? c1 : c0;
            c = gv*iv + c*fv;
            float h = tanh_fast(c) * ov;
            sH[b*UPC + uu] = __float2half_rn(h);
            if (t == TSEQ-1) g_h32[(bg*MB + b)*HID + ug*UPC + uu] = h;
        }
        __syncthreads();

        // ---- Push own h slice to all ranks' buffer p^1 + remote arrive (warp w -> rank w) ----
        if (t < TSEQ-1) {
            const int q = p ^ 1;
            #pragma unroll
            for (int j = 0; j < 2; ++j) {
                int c    = lid + j*32;        // chunk 0..63
                int row  = c >> 2;
                int q4   = c & 3;
                uint4 v = *(const uint4*)((const unsigned char*)sH + row*64 + q4*16);
                uint32_t dst_local = smb + OFF_SA +
                    (uint32_t)((q*SA_ELEMS + row*KPAD + ug*UPC + q4*8) * 2);
                remote_st_v4(dst_local, (uint32_t)warp, v);
            }
            __syncwarp();
            if (elect1())
                remote_arrive(smb + OFF_MBAR + q*8, (uint32_t)warp);
        }

        // ---- Phase X for step t+1: fc = x_{t+1} @ Wx^T (buffer p^1) — overlaps comm ----
        wmma::fill_fragment(fc, 0.0f);
        const __half* sAx = sA + (p^1)*SA_ELEMS;
        #pragma unroll
        for (int kk = KH; kk < KSTEPS; ++kk) {
            wmma::load_matrix_sync(fa, sAx + kk*16, KPAD);
            wmma::mma_sync(fc, fa, fbr[kk], fc);
        }

        // ---- stage x_{t+2} into buffer p x-region ----
        {
            int row = tid >> 4;
            int q   = (tid & 15) * 8;
            __half2 h0 = __floats2half2_rn(xv0.x, xv0.y), h1 = __floats2half2_rn(xv0.z, xv0.w);
            __half2 h2 = __floats2half2_rn(xv1.x, xv1.y), h3 = __floats2half2_rn(xv1.z, xv1.w);
            uint4 pk; pk.x = *(uint32_t*)&h0; pk.y = *(uint32_t*)&h1;
            pk.z = *(uint32_t*)&h2; pk.w = *(uint32_t*)&h3;
            *(uint4*)&sA[p*SA_ELEMS + row*KPAD + HID + q] = pk;
        }
    }

    // ---- make g_h32 visible; keep cluster alive until all pushes/reads done ----
    __threadfence();
    asm volatile("barrier.cluster.arrive.aligned;" ::: "memory");
    asm volatile("barrier.cluster.wait.aligned;"   ::: "memory");

    // ---- Final projection: out = h_T @ Wp^T + bp (fp32), rank-0 CTAs ----
    if (ug == 0) {
        const int b     = tid >> 4;
        const int obase = (tid & 15) * 8;
        float acc[8];
        #pragma unroll
        for (int rr = 0; rr < 8; ++rr) acc[rr] = bp[obase + rr];
        const float* hrow = &g_h32[(bg*MB + b)*HID];
        for (int k = 0; k < HID; ++k) {
            float hv = hrow[k];
            #pragma unroll
            for (int rr = 0; rr < 8; ++rr)
                acc[rr] = fmaf(hv, Wp[(obase + rr)*HID + k], acc[rr]);
        }
        #pragma unroll
        for (int rr = 0; rr < 8; ++rr)
            out[(bg*MB + b)*OUT_D + obase + rr] = acc[rr];
    }
}

extern "C" void kernel_launch(void* const* d_in, const int* in_sizes, int n_in,
                              void* d_out, int out_size) {
    const float* x   = (const float*)d_in[0];
    const float* Wgx = (const float*)d_in[1];
    const float* bgx = (const float*)d_in[2];
    const float* Wgh = (const float*)d_in[3];
    const float* Wix = (const float*)d_in[4];
    const float* bix = (const float*)d_in[5];
    const float* Wih = (const float*)d_in[6];
    const float* Wfx = (const float*)d_in[7];
    const float* bfx = (const float*)d_in[8];
    const float* Wfh = (const float*)d_in[9];
    const float* Wox = (const float*)d_in[10];
    const float* box = (const float*)d_in[11];
    const float* Woh = (const float*)d_in[12];
    const float* Wp  = (const float*)d_in[13];
    const float* bp  = (const float*)d_in[14];
    float* out = (float*)d_out;

    static bool attr_set = false;
    if (!attr_set) {
        cudaFuncSetAttribute(lstm_mb_kernel,
                             cudaFuncAttributeMaxDynamicSharedMemorySize, SMEM_BYTES);
        attr_set = true;
    }

    lstm_mb_kernel<<<NBG*NUG, NTH, SMEM_BYTES>>>(
        x, Wgx, bgx, Wgh, Wix, bix, Wih, Wfx, bfx, Wfh, Wox, box, Woh, Wp, bp, out);
}